// round 6
// baseline (speedup 1.0000x reference)
#include <cuda_runtime.h>

#define NUSERS 100000
#define NITEMS 50000
#define NNODES 150000
#define NEDGES 1200000
#define NV4    (NNODES * 16)        // float4 slots per embedding buffer
#define SCAN_B 1024
#define NBLK   ((NNODES + SCAN_B - 1) / SCAN_B)   // 147

// Mid-layer embedding buffers (2 x 38.4 MB) + CSR scratch. Static globals only.
__device__ __align__(16) float4 g_e1[NV4];
__device__ __align__(16) float4 g_e2[NV4];
__device__ int  g_cnt[NNODES];
__device__ int  g_pos[NNODES];
__device__ int  g_rowptr[NNODES + 1];   // block-local exclusive prefix (add g_bsum)
__device__ int  g_bsum[NBLK];           // exclusive prefix of per-block totals
__device__ __align__(8) int2 g_edges[NEDGES];   // {col, __float_as_int(0.8*val)}

// ---- node read for layer 0 (virtual concat of ue/ie, no materialization) ----
__device__ __forceinline__ float4 node0_f4(const float4* __restrict__ ue4,
                                           const float4* __restrict__ ie4,
                                           int n, int sub) {
    return (n < NUSERS) ? ue4[n * 16 + sub] : ie4[(n - NUSERS) * 16 + sub];
}

__global__ __launch_bounds__(256) void k_zero() {
    int i = blockIdx.x * 256 + threadIdx.x;
    if (i < NNODES) { g_cnt[i] = 0; g_pos[i] = 0; }
}

__global__ __launch_bounds__(256) void k_hist(const int* __restrict__ er) {
    int e = blockIdx.x * 256 + threadIdx.x;
    if (e < NEDGES) atomicAdd(&g_cnt[er[e]], 1);
}

// Per-block exclusive scan of g_cnt -> g_rowptr; per-block totals -> g_bsum slot.
__global__ __launch_bounds__(SCAN_B) void k_scan1() {
    __shared__ int sh[SCAN_B];
    int idx = blockIdx.x * SCAN_B + threadIdx.x;
    int v = (idx < NNODES) ? g_cnt[idx] : 0;
    sh[threadIdx.x] = v;
    __syncthreads();
    #pragma unroll
    for (int o = 1; o < SCAN_B; o <<= 1) {
        int t = (threadIdx.x >= o) ? sh[threadIdx.x - o] : 0;
        __syncthreads();
        sh[threadIdx.x] += t;
        __syncthreads();
    }
    int incl = sh[threadIdx.x];
    if (idx <= NNODES) g_rowptr[idx] = incl - v;          // block-local exclusive
    if (threadIdx.x == SCAN_B - 1) g_bsum[blockIdx.x] = incl;  // block total
}

// Parallel exclusive scan of the 147 block totals (one block).
__global__ __launch_bounds__(256) void k_scan2() {
    __shared__ int sh[256];
    int i = threadIdx.x;
    int v = (i < NBLK) ? g_bsum[i] : 0;
    sh[i] = v;
    __syncthreads();
    #pragma unroll
    for (int o = 1; o < 256; o <<= 1) {
        int t = (i >= o) ? sh[i - o] : 0;
        __syncthreads();
        sh[i] += t;
        __syncthreads();
    }
    if (i < NBLK) g_bsum[i] = sh[i] - v;                  // exclusive
}

// Place each edge into its row segment (order within row arbitrary).
__global__ __launch_bounds__(256) void k_reorder(const int* __restrict__ er,
                                                 const int* __restrict__ ec,
                                                 const float* __restrict__ ev) {
    int e = blockIdx.x * 256 + threadIdx.x;
    if (e >= NEDGES) return;
    int row = er[e];
    int base = g_rowptr[row] + g_bsum[row >> 10];
    int pos  = base + atomicAdd(&g_pos[row], 1);
    g_edges[pos] = make_int2(ec[e], __float_as_int(ev[e] * 0.8f));
}

__device__ __forceinline__ void row_range(int row, int& beg, int& end) {
    beg = g_rowptr[row]     + g_bsum[row >> 10];
    end = g_rowptr[row + 1] + g_bsum[(row + 1) >> 10];
}

// Layer 1: e1[row] = 0.2*e0[row] + sum 0.8v*e0[col], e0 read from ue/ie directly.
__global__ __launch_bounds__(256) void k_prop0(const float4* __restrict__ ue4,
                                               const float4* __restrict__ ie4) {
    int t   = blockIdx.x * 256 + threadIdx.x;
    int row = t >> 4;
    if (row >= NNODES) return;
    int sub = t & 15;
    int beg, end; row_range(row, beg, end);

    float4 own = node0_f4(ue4, ie4, row, sub);
    float4 s = make_float4(0.2f * own.x, 0.2f * own.y, 0.2f * own.z, 0.2f * own.w);

    int e = beg;
    for (; e + 1 < end; e += 2) {
        int2 p0 = g_edges[e];
        int2 p1 = g_edges[e + 1];
        float4 x0 = node0_f4(ue4, ie4, p0.x, sub);
        float4 x1 = node0_f4(ue4, ie4, p1.x, sub);
        float v0 = __int_as_float(p0.y);
        float v1 = __int_as_float(p1.y);
        s.x += v0 * x0.x; s.y += v0 * x0.y; s.z += v0 * x0.z; s.w += v0 * x0.w;
        s.x += v1 * x1.x; s.y += v1 * x1.y; s.z += v1 * x1.z; s.w += v1 * x1.w;
    }
    if (e < end) {
        int2 p0 = g_edges[e];
        float4 x0 = node0_f4(ue4, ie4, p0.x, sub);
        float v0 = __int_as_float(p0.y);
        s.x += v0 * x0.x; s.y += v0 * x0.y; s.z += v0 * x0.z; s.w += v0 * x0.w;
    }
    g_e1[row * 16 + sub] = s;
}

// Layer 2: e2 = prop(e1).
__global__ __launch_bounds__(256) void k_prop1() {
    int t   = blockIdx.x * 256 + threadIdx.x;
    int row = t >> 4;
    if (row >= NNODES) return;
    int sub = t & 15;
    int beg, end; row_range(row, beg, end);

    const float4* __restrict__ src = g_e1;
    float4 own = src[row * 16 + sub];
    float4 s = make_float4(0.2f * own.x, 0.2f * own.y, 0.2f * own.z, 0.2f * own.w);

    int e = beg;
    for (; e + 1 < end; e += 2) {
        int2 p0 = g_edges[e];
        int2 p1 = g_edges[e + 1];
        float4 x0 = src[p0.x * 16 + sub];
        float4 x1 = src[p1.x * 16 + sub];
        float v0 = __int_as_float(p0.y);
        float v1 = __int_as_float(p1.y);
        s.x += v0 * x0.x; s.y += v0 * x0.y; s.z += v0 * x0.z; s.w += v0 * x0.w;
        s.x += v1 * x1.x; s.y += v1 * x1.y; s.z += v1 * x1.z; s.w += v1 * x1.w;
    }
    if (e < end) {
        int2 p0 = g_edges[e];
        float4 x0 = src[p0.x * 16 + sub];
        float v0 = __int_as_float(p0.y);
        s.x += v0 * x0.x; s.y += v0 * x0.y; s.z += v0 * x0.z; s.w += v0 * x0.w;
    }
    g_e2[row * 16 + sub] = s;
}

// acc(n) = e0[n] + e1[n] + e2[n] + e3[n], with e3 computed on the fly from e2.
// One float2 per lane (32 lanes x 2 = 64 dims).
__device__ __forceinline__ float2 node_acc(int n, int lane,
                                           const float2* __restrict__ ue2,
                                           const float2* __restrict__ ie2) {
    const float2* __restrict__ E1 = (const float2*)g_e1;
    const float2* __restrict__ E2 = (const float2*)g_e2;
    float2 z0 = (n < NUSERS) ? ue2[n * 32 + lane] : ie2[(n - NUSERS) * 32 + lane];
    float2 z1 = E1[n * 32 + lane];
    float2 z2 = E2[n * 32 + lane];
    // e3 = 0.2*e2[n] + sum 0.8v*e2[col]
    float2 z3 = make_float2(0.2f * z2.x, 0.2f * z2.y);
    int beg, end; row_range(n, beg, end);
    int e = beg;
    for (; e + 1 < end; e += 2) {
        int2 p0 = g_edges[e];
        int2 p1 = g_edges[e + 1];
        float2 x0 = E2[p0.x * 32 + lane];
        float2 x1 = E2[p1.x * 32 + lane];
        float v0 = __int_as_float(p0.y);
        float v1 = __int_as_float(p1.y);
        z3.x += v0 * x0.x; z3.y += v0 * x0.y;
        z3.x += v1 * x1.x; z3.y += v1 * x1.y;
    }
    if (e < end) {
        int2 p0 = g_edges[e];
        float2 x0 = E2[p0.x * 32 + lane];
        float v0 = __int_as_float(p0.y);
        z3.x += v0 * x0.x; z3.y += v0 * x0.y;
    }
    return make_float2(z0.x + z1.x + z2.x + z3.x, z0.y + z1.y + z2.y + z3.y);
}

// gamma[w] = dot(acc(u), acc(NUSERS+i)) / 16
__global__ __launch_bounds__(256) void k_gamma(const int* __restrict__ users,
                                               const int* __restrict__ items,
                                               const float* __restrict__ ue,
                                               const float* __restrict__ ie,
                                               float* __restrict__ out) {
    int w    = (blockIdx.x * 256 + threadIdx.x) >> 5;   // warp per output pair
    int lane = threadIdx.x & 31;
    if (w >= 4096) return;
    const float2* ue2 = (const float2*)ue;
    const float2* ie2 = (const float2*)ie;
    float2 a = node_acc(users[w],          lane, ue2, ie2);
    float2 b = node_acc(NUSERS + items[w], lane, ue2, ie2);
    float s = a.x * b.x + a.y * b.y;
    #pragma unroll
    for (int o = 16; o; o >>= 1) s += __shfl_xor_sync(0xffffffffu, s, o);
    if (lane == 0) out[w] = s * (1.0f / 16.0f);
}

extern "C" void kernel_launch(void* const* d_in, const int* in_sizes, int n_in,
                              void* d_out, int out_size) {
    const int*   users = (const int*)  d_in[0];
    const int*   items = (const int*)  d_in[1];
    const int*   er    = (const int*)  d_in[2];
    const int*   ec    = (const int*)  d_in[3];
    const float* ev    = (const float*)d_in[4];
    const float* ue    = (const float*)d_in[5];
    const float* ie    = (const float*)d_in[6];
    float* out = (float*)d_out;

    const int PROP_BLOCKS = (NV4 + 255) / 256;        // 9375 (16 lanes/row)
    const int EDGE_BLOCKS = (NEDGES + 255) / 256;     // 4688

    k_zero<<<(NNODES + 255) / 256, 256>>>();
    k_hist<<<EDGE_BLOCKS, 256>>>(er);
    k_scan1<<<NBLK, SCAN_B>>>();
    k_scan2<<<1, 256>>>();
    k_reorder<<<EDGE_BLOCKS, 256>>>(er, ec, ev);

    k_prop0<<<PROP_BLOCKS, 256>>>((const float4*)ue, (const float4*)ie);
    k_prop1<<<PROP_BLOCKS, 256>>>();

    k_gamma<<<4096 / 8, 256>>>(users, items, ue, ie, out);
}